// round 6
// baseline (speedup 1.0000x reference)
#include <cuda_runtime.h>

#define NPIX 16384   // 128*128 ROI pixels
#define NS   64      // sensors
#define NT   2030    // time samples
#define NB   64      // batch
#define BQ   8       // batches per block
#define SNT  (NS*NT) // sinogram batch stride = 129920

// Tile-order, pre-masked geometry: [s][gidx]
__device__ int   g_tT[NS * NPIX];
__device__ float g_wT[NS * NPIX];
__device__ float g_bmax[NB];

// Tile-order index: block(rg,cg) of 8 rows x 32 cols; warp = 8 rows x 4 cols.
__device__ __forceinline__ int gidx_of(int pix) {
    int x = pix & 127, y = pix >> 7;
    return (((y >> 3) << 2) + (x >> 5)) * 256
         + (((x >> 2) & 7) << 5) + ((y & 7) << 2) + (x & 3);
}

// Transpose [pix][s] -> tile-ordered [s][gidx], baking clamp + validity.
// Also zero-inits g_bmax.
__global__ __launch_bounds__(1024) void prep_kernel(
    const float* __restrict__ wts, const int* __restrict__ tidx)
{
    __shared__ int   ts[32][33];
    __shared__ float ws[32][33];
    const int p0 = blockIdx.x * 32;
    const int s0 = blockIdx.y * 32;
    const int tx = threadIdx.x, ty = threadIdx.y;

    if (blockIdx.x == 0 && blockIdx.y == 0 && ty < 2)
        g_bmax[ty * 32 + tx] = 0.0f;

    int   t = tidx[(p0 + ty) * NS + s0 + tx];
    float w = wts [(p0 + ty) * NS + s0 + tx];
    w = (t >= 0 && t < NT) ? w : 0.0f;
    t = min(max(t, 0), NT - 1);
    ts[ty][tx] = t;
    ws[ty][tx] = w;
    __syncthreads();

    const int gi = gidx_of(p0 + tx);
    g_tT[(s0 + ty) * NPIX + gi] = ts[tx][ty];
    g_wT[(s0 + ty) * NPIX + gi] = ws[tx][ty];
}

__global__ __launch_bounds__(256) void das_kernel(
    const float* __restrict__ sino,   // [NB, NS, NT]
    float*       __restrict__ out)    // [NB*NPIX das | NB*NS*NPIX pixel_interp]
{
    __shared__ float stg[2][BQ][256];  // double-buffered 8KB exchange buffers
    __shared__ float smax[8][BQ];

    const int tid = threadIdx.x;
    const int l   = tid & 31;
    const int gw  = tid >> 5;              // warp id
    const int cg  = blockIdx.x & 3;        // col group (32 px)
    const int rg  = blockIdx.x >> 2;       // row group (8 rows)
    const int b0  = blockIdx.y * BQ;

    // gather-role pixel (tile order: warp = 8 rows x 4 cols)
    const int y    = rg * 8 + (l >> 2);
    const int x    = cg * 32 + gw * 4 + (l & 3);
    const int pix  = y * 128 + x;
    const int gidx = blockIdx.x * 256 + tid;

    // store-role: warp gw stores row (rg*8+gw), lane l -> col cg*32+l
    const int spix = (rg * 8 + gw) * 128 + cg * 32 + l;
    // conflict-free swizzled cells (verified bijections, both roles 1 wf)
    const int rd_cell = ((l >> 2) << 5) + (((gw << 2) + (l & 3)) ^ ((l >> 2) << 2));
    const int wr_cell = (gw << 5) + (l ^ (gw << 2));

    const float* __restrict__ sb = sino + b0 * SNT;
    float* __restrict__ pib = out + NB * NPIX + (size_t)(b0 * NS) * NPIX + spix;

    float acc[BQ];
    #pragma unroll
    for (int q = 0; q < BQ; ++q) acc[q] = 0.0f;

    // ---- prologue: gather s = 0 ----
    float v[BQ];
    {
        const int   t = g_tT[gidx];
        const float w = g_wT[gidx];
        const float* __restrict__ src = sb + t;
        #pragma unroll
        for (int q = 0; q < BQ; ++q) v[q] = __ldg(src + q * SNT) * w;
    }

    for (int s = 0; s < NS; ++s) {
        // ---- issue next sensor's gathers (overlap with exchange below) ----
        float vn[BQ];
        if (s + 1 < NS) {
            const int   tn = g_tT[(s + 1) * NPIX + gidx];
            const float wn = g_wT[(s + 1) * NPIX + gidx];
            const float* __restrict__ srcn = sb + (s + 1) * NT + tn;
            #pragma unroll
            for (int q = 0; q < BQ; ++q) vn[q] = __ldg(srcn + q * SNT) * wn;
        }

        // ---- exchange + coalesced store for sensor s ----
        const int p = s & 1;
        #pragma unroll
        for (int q = 0; q < BQ; ++q) {
            acc[q] += v[q];
            stg[p][q][wr_cell] = v[q];
        }
        __syncthreads();     // single barrier: also guards buf 1-p reuse next iter

        const size_t po = (size_t)s * NPIX;
        #pragma unroll
        for (int q = 0; q < BQ; ++q)
            pib[po + (size_t)q * (NS * NPIX)] = stg[p][q][rd_cell];

        #pragma unroll
        for (int q = 0; q < BQ; ++q) v[q] = vn[q];
    }

    // ---- das = relu(sum), raw store + per-batch max ----
    float bm[BQ];
    #pragma unroll
    for (int q = 0; q < BQ; ++q) {
        float d = fmaxf(acc[q], 0.0f);
        out[(size_t)(b0 + q) * NPIX + pix] = d;
        bm[q] = d;
    }
    #pragma unroll
    for (int q = 0; q < BQ; ++q) {
        float m = bm[q];
        #pragma unroll
        for (int off = 16; off > 0; off >>= 1)
            m = fmaxf(m, __shfl_xor_sync(0xffffffffu, m, off));
        if (l == 0) smax[gw][q] = m;
    }
    __syncthreads();
    if (tid < BQ) {
        float m = smax[0][tid];
        #pragma unroll
        for (int wq = 1; wq < 8; ++wq) m = fmaxf(m, smax[wq][tid]);
        atomicMax(reinterpret_cast<int*>(&g_bmax[b0 + tid]),
                  __float_as_int(m));
    }
}

__global__ __launch_bounds__(256) void norm_kernel(float* __restrict__ out)
{
    int i = blockIdx.x * blockDim.x + threadIdx.x;
    float4* p = reinterpret_cast<float4*>(out);
    float4 v = p[i];
    int b = (i * 4) >> 14;
    float m = g_bmax[b];
    float r = (m > 1e-8f) ? (1.0f / m) : 1.0f;
    v.x *= r; v.y *= r; v.z *= r; v.w *= r;
    p[i] = v;
}

extern "C" void kernel_launch(void* const* d_in, const int* in_sizes, int n_in,
                              void* d_out, int out_size)
{
    const float* sino = (const float*)d_in[0];   // [64,1,64,2030]
    const float* wts  = (const float*)d_in[1];   // [128,128,64]
    const int*   tidx = (const int*)d_in[2];     // [128,128,64]
    float* out = (float*)d_out;

    dim3 pgrid(NPIX / 32, NS / 32);               // (512, 2)
    prep_kernel<<<pgrid, dim3(32, 32)>>>(wts, tidx);

    dim3 grid(64, NB / BQ);                       // 512 blocks, 1 wave
    das_kernel<<<grid, 256>>>(sino, out);

    norm_kernel<<<(NB * NPIX / 4) / 256, 256>>>(out);
}